// round 1
// baseline (speedup 1.0000x reference)
#include <cuda_runtime.h>

#define N_ANCH 5000
#define N_CLS 80
#define WORDS 157          // ceil(5000/32)
#define WSTRIDE 160        // padded row stride (640B, 128B-aligned)
#define MAXB 300
#define SCORE_THR_F 0.05f
#define OUT_COLS 84

// 3.2 MB suppression bitmask: bit j of word w of row i  <=>  iou(i, 32w+j) > 0.5 && i != 32w+j
__device__ unsigned int g_mask[N_ANCH * WSTRIDE];
// per-class kept bitmask
__device__ unsigned int g_kept[N_CLS * WSTRIDE];

// ---------------------------------------------------------------------------
// Kernel A: IoU > 0.5 bitmask, warp per anchor row. Exact IEEE fp32 ops
// (no FMA contraction, correctly-rounded division) to match the reference.
// ---------------------------------------------------------------------------
__global__ void iou_mask_kernel(const float4* __restrict__ boxes) {
    int warp = (blockIdx.x * blockDim.x + threadIdx.x) >> 5;
    int lane = threadIdx.x & 31;
    if (warp >= N_ANCH) return;

    float4 bi = boxes[warp];
    float ai = __fmul_rn(__fsub_rn(bi.z, bi.x), __fsub_rn(bi.w, bi.y));

    for (int w = 0; w < WORDS; ++w) {
        int j = (w << 5) + lane;
        bool in = (j < N_ANCH);
        float4 bj = boxes[in ? j : 0];

        float iw = fmaxf(__fsub_rn(fminf(bi.z, bj.z), fmaxf(bi.x, bj.x)), 0.0f);
        float ih = fmaxf(__fsub_rn(fminf(bi.w, bj.w), fmaxf(bi.y, bj.y)), 0.0f);
        float inter = __fmul_rn(iw, ih);
        float aj = __fmul_rn(__fsub_rn(bj.z, bj.x), __fsub_rn(bj.w, bj.y));
        float uni = __fsub_rn(__fadd_rn(ai, aj), inter);  // >= 1 always (areas >= 1)

        bool pred = false;
        // conservative prefilter: true iou>0.5 implies inter > 0.49999*uni >> 0.25*uni
        if (inter > __fmul_rn(0.25f, uni)) {
            float iou = __fdiv_rn(inter, fmaxf(uni, 1e-8f));
            pred = (iou > 0.5f);
        }
        pred = pred && in && (j != warp);

        unsigned int m = __ballot_sync(0xffffffffu, pred);
        if (lane == 0) g_mask[warp * WSTRIDE + w] = m;
    }
}

// ---------------------------------------------------------------------------
// Kernel B: one block per class. Filter (score > thr) -> stable descending
// bitonic sort of (score_bits, ~idx) keys in shared -> warp-windowed greedy
// scan using the precomputed suppression bitmask.
// ---------------------------------------------------------------------------
#define SORT_THREADS 512

__global__ void __launch_bounds__(SORT_THREADS, 1)
nms_class_kernel(const float* __restrict__ cls) {
    extern __shared__ unsigned long long sh[];
    unsigned long long* keys = sh;                         // up to 8192 keys
    unsigned int* supp = (unsigned int*)&keys[8192];       // WSTRIDE words
    unsigned int* kept = supp + WSTRIDE;                   // WSTRIDE words
    __shared__ int s_cnt;

    const int c = blockIdx.x;
    const int tid = threadIdx.x;

    if (tid == 0) s_cnt = 0;
    for (int w = tid; w < WSTRIDE; w += blockDim.x) { supp[w] = 0u; kept[w] = 0u; }
    __syncthreads();

    // filter + pack keys: (score_bits << 32) | (0xFFFFFFFF - idx)
    // scores >= 0 so float bits order == float order; low word breaks ties
    // toward LOWER index first under descending sort (jnp.argsort stability).
    for (int i = tid; i < N_ANCH; i += blockDim.x) {
        float s = cls[i * N_CLS + c];
        if (s > SCORE_THR_F) {
            int p = atomicAdd(&s_cnt, 1);
            keys[p] = ((unsigned long long)__float_as_uint(s) << 32) |
                      (unsigned long long)(0xFFFFFFFFu - (unsigned int)i);
        }
    }
    __syncthreads();
    const int cnt = s_cnt;

    if (cnt > 0) {
        // pad to power of 2 with 0-keys (sort to the tail)
        int n = 1; while (n < cnt) n <<= 1;
        for (int i = cnt + tid; i < n; i += blockDim.x) keys[i] = 0ull;
        __syncthreads();

        // bitonic sort, descending
        for (int k = 2; k <= n; k <<= 1) {
            for (int j = k >> 1; j > 0; j >>= 1) {
                for (int i = tid; i < n; i += blockDim.x) {
                    int ixj = i ^ j;
                    if (ixj > i) {
                        unsigned long long a = keys[i];
                        unsigned long long b = keys[ixj];
                        bool desc = ((i & k) == 0);
                        if ((a < b) == desc) { keys[i] = b; keys[ixj] = a; }
                    }
                }
                __syncthreads();
            }
        }

        // greedy scan: warp 0, 32-candidate windows
        if (tid < 32) {
            const int lane = tid;
            int count = 0;
            for (int base = 0; base < cnt && count < MAXB; base += 32) {
                int p = base + lane;
                bool has = (p < cnt);
                unsigned long long key = has ? keys[p] : 0ull;
                int idx = (int)(0xFFFFFFFFu - (unsigned int)(key & 0xFFFFFFFFull));
                unsigned int pend = __ballot_sync(0xffffffffu, has);

                while (pend) {
                    bool sup = has && ((supp[idx >> 5] >> (idx & 31)) & 1u);
                    unsigned int alive = pend & ~__ballot_sync(0xffffffffu, sup);
                    if (!alive) break;
                    int f = __ffs(alive) - 1;
                    int kidx = __shfl_sync(0xffffffffu, idx, f);
                    if (lane == f) kept[idx >> 5] |= (1u << (idx & 31));
                    count++;
                    const unsigned int* rowm = &g_mask[kidx * WSTRIDE];
                    #pragma unroll
                    for (int w = lane; w < WORDS; w += 32)
                        supp[w] |= rowm[w];
                    __syncwarp(0xffffffffu);
                    pend = alive & ~(1u << f);
                    if (count >= MAXB) break;
                }
            }
        }
    }
    __syncthreads();

    for (int w = tid; w < WSTRIDE; w += blockDim.x)
        g_kept[c * WSTRIDE + w] = kept[w];
}

// ---------------------------------------------------------------------------
// Kernel C: assemble output (1, 5000, 84) = [boxes | kept ? score : 0]
// ---------------------------------------------------------------------------
__global__ void assemble_kernel(const float* __restrict__ boxes,
                                const float* __restrict__ cls,
                                float* __restrict__ out) {
    int t = blockIdx.x * blockDim.x + threadIdx.x;
    if (t >= N_ANCH * OUT_COLS) return;
    int i = t / OUT_COLS;
    int col = t - i * OUT_COLS;
    float v;
    if (col < 4) {
        v = boxes[i * 4 + col];
    } else {
        int cc = col - 4;
        float s = cls[i * N_CLS + cc];
        unsigned int m = g_kept[cc * WSTRIDE + (i >> 5)];
        v = ((m >> (i & 31)) & 1u) ? s : 0.0f;
    }
    out[t] = v;
}

// ---------------------------------------------------------------------------
extern "C" void kernel_launch(void* const* d_in, const int* in_sizes, int n_in,
                              void* d_out, int out_size) {
    const float* boxes = (const float*)d_in[0];          // (1,5000,4) f32
    const float* cls   = (const float*)d_in[1];          // (1,5000,80) f32
    float* out = (float*)d_out;                          // (1,5000,84) f32

    // Kernel A: warp per anchor row
    {
        int threads = 256;
        int total = N_ANCH * 32;
        iou_mask_kernel<<<(total + threads - 1) / threads, threads>>>(
            (const float4*)boxes);
    }

    // Kernel B: block per class, dynamic shared (keys + bitmaps)
    {
        size_t smem = 8192ull * 8ull + 2ull * WSTRIDE * 4ull;  // 66816 B
        cudaFuncSetAttribute(nms_class_kernel,
                             cudaFuncAttributeMaxDynamicSharedMemorySize,
                             (int)smem);
        nms_class_kernel<<<N_CLS, SORT_THREADS, smem>>>(cls);
    }

    // Kernel C: assemble
    {
        int total = N_ANCH * OUT_COLS;
        int threads = 256;
        assemble_kernel<<<(total + threads - 1) / threads, threads>>>(
            boxes, cls, out);
    }
}